// round 1
// baseline (speedup 1.0000x reference)
#include <cuda_runtime.h>
#include <math.h>

#define Bc    8
#define Hc    128
#define Wc    128
#define Dc    256
#define Nc    8192
#define MLPW  256
#define INDIM 813          // 2 + 40 + 768 + 3
#define TILE  32
#define SMEM_BYTES (INDIM * TILE * 4)

// ---------------- device scratch (static, allowed) ----------------
__device__ float g_t1[Bc * Hc * 64 * Dc];   // W-pass 128->64   (67 MB)
__device__ float g_l1[Bc * 64 * 64 * Dc];   // level1           (33 MB)
__device__ float g_t2[Bc * Hc * 32 * Dc];   // W-pass 128->32   (33 MB)
__device__ float g_l2[Bc * 32 * 32 * Dc];   // level2           (8 MB)
__device__ float g_film[Bc * 2 * MLPW];     // ctx @ ctx_w + ctx_b

// ---------------- separable antialiased triangle resize ----------------
// jax.image.resize(bilinear, antialias=True): sample_f = (o+0.5)*INV - 0.5,
// taps j with |j-sample_f| < INV, w = 1 - |j-sf|/INV, renormalized over
// in-range taps.
template <int INV, int HL, int WIN>
__device__ __forceinline__ void resize_w_body(const float* __restrict__ in,
                                              float* __restrict__ out) {
    const int WOUT = WIN / INV;
    const int NT = 2 * INV;
    int idx = blockIdx.x * blockDim.x + threadIdx.x;
    if (idx >= Bc * HL * WOUT * (Dc / 4)) return;
    int d4 = idx & 63;
    int t = idx >> 6;
    int xo = t % WOUT; t /= WOUT;
    int y = t % HL;
    int b = t / HL;

    float sf = (xo + 0.5f) * INV - 0.5f;
    int j0 = INV * xo - (INV / 2);
    float w[NT];
    float wsum = 0.f;
#pragma unroll
    for (int i = 0; i < NT; i++) {
        int j = j0 + i;
        float ww = 1.0f - fabsf((float)j - sf) * (1.0f / INV);
        ww = (j >= 0 && j < WIN) ? fmaxf(ww, 0.f) : 0.f;
        w[i] = ww;
        wsum += ww;
    }
    float inv = 1.0f / wsum;
    const float4* ip = (const float4*)in + ((size_t)(b * HL + y) * WIN) * 64 + d4;
    float4 acc = make_float4(0.f, 0.f, 0.f, 0.f);
#pragma unroll
    for (int i = 0; i < NT; i++) {
        if (w[i] > 0.f) {
            float4 v = __ldg(&ip[(j0 + i) * 64]);
            float ww = w[i] * inv;
            acc.x += ww * v.x; acc.y += ww * v.y;
            acc.z += ww * v.z; acc.w += ww * v.w;
        }
    }
    ((float4*)out)[((size_t)(b * HL + y) * WOUT + xo) * 64 + d4] = acc;
}

template <int INV, int HIN, int WL>
__device__ __forceinline__ void resize_h_body(const float* __restrict__ in,
                                              float* __restrict__ out) {
    const int HOUT = HIN / INV;
    const int NT = 2 * INV;
    int idx = blockIdx.x * blockDim.x + threadIdx.x;
    if (idx >= Bc * HOUT * WL * (Dc / 4)) return;
    int d4 = idx & 63;
    int t = idx >> 6;
    int x = t % WL; t /= WL;
    int yo = t % HOUT;
    int b = t / HOUT;

    float sf = (yo + 0.5f) * INV - 0.5f;
    int j0 = INV * yo - (INV / 2);
    float w[NT];
    float wsum = 0.f;
#pragma unroll
    for (int i = 0; i < NT; i++) {
        int j = j0 + i;
        float ww = 1.0f - fabsf((float)j - sf) * (1.0f / INV);
        ww = (j >= 0 && j < HIN) ? fmaxf(ww, 0.f) : 0.f;
        w[i] = ww;
        wsum += ww;
    }
    float inv = 1.0f / wsum;
    const float4* ip = (const float4*)in + ((size_t)b * HIN * WL + x) * 64 + d4;
    float4 acc = make_float4(0.f, 0.f, 0.f, 0.f);
#pragma unroll
    for (int i = 0; i < NT; i++) {
        if (w[i] > 0.f) {
            float4 v = __ldg(&ip[(size_t)(j0 + i) * WL * 64]);
            float ww = w[i] * inv;
            acc.x += ww * v.x; acc.y += ww * v.y;
            acc.z += ww * v.z; acc.w += ww * v.w;
        }
    }
    ((float4*)out)[((size_t)(b * HOUT + yo) * WL + x) * 64 + d4] = acc;
}

__global__ void resize_w2_kernel(const float* __restrict__ in) { resize_w_body<2, Hc, Wc>(in, g_t1); }
__global__ void resize_h2_kernel() { resize_h_body<2, Hc, 64>(g_t1, g_l1); }
__global__ void resize_w4_kernel(const float* __restrict__ in) { resize_w_body<4, Hc, Wc>(in, g_t2); }
__global__ void resize_h4_kernel() { resize_h_body<4, Hc, 32>(g_t2, g_l2); }

// ---------------- FiLM: ctx = context_vector @ ctx_w + ctx_b ----------------
__global__ void film_kernel(const float* __restrict__ cv,
                            const float* __restrict__ cw,
                            const float* __restrict__ cb) {
    int b = blockIdx.x;
    int j = threadIdx.x;             // 512 threads
    float acc = cb[j];
    for (int k = 0; k < Dc; k++)
        acc = fmaf(cv[b * Dc + k], cw[k * 512 + j], acc);
    g_film[b * 512 + j] = acc;
}

// ---------------- fused gather + MLP ----------------
__device__ __forceinline__ float gelu_t(float x) {
    // jax.nn.gelu (approximate=True)
    float x3 = x * x * x;
    float t = tanhf(0.7978845608028654f * (x + 0.044715f * x3));
    return 0.5f * x * (1.0f + t);
}

#define GEMM_STEP(WK, KIDX)                                        \
    {                                                              \
        const float4* hr = (const float4*)(hbuf + (KIDX) * TILE);  \
        _Pragma("unroll")                                          \
        for (int j = 0; j < 8; j++) {                              \
            float4 hv = hr[j];                                     \
            acc[4 * j + 0] = fmaf(WK, hv.x, acc[4 * j + 0]);       \
            acc[4 * j + 1] = fmaf(WK, hv.y, acc[4 * j + 1]);       \
            acc[4 * j + 2] = fmaf(WK, hv.z, acc[4 * j + 2]);       \
            acc[4 * j + 3] = fmaf(WK, hv.w, acc[4 * j + 3]);       \
        }                                                          \
    }

__device__ __forceinline__ void gemm_cols(const float* __restrict__ hbuf,
                                          const float* __restrict__ wcol,
                                          int K, float* acc) {
#pragma unroll
    for (int r = 0; r < TILE; r++) acc[r] = 0.f;
    int k = 0;
    for (; k + 4 <= K; k += 4) {
        float w0 = __ldg(wcol + (k + 0) * MLPW);
        float w1 = __ldg(wcol + (k + 1) * MLPW);
        float w2 = __ldg(wcol + (k + 2) * MLPW);
        float w3 = __ldg(wcol + (k + 3) * MLPW);
        GEMM_STEP(w0, k + 0)
        GEMM_STEP(w1, k + 1)
        GEMM_STEP(w2, k + 2)
        GEMM_STEP(w3, k + 3)
    }
    for (; k < K; k++) {
        float wv = __ldg(wcol + k * MLPW);
        GEMM_STEP(wv, k)
    }
}

__global__ void __launch_bounds__(256)
fused_kernel(const float* __restrict__ grid,
             const float* __restrict__ coords,
             const float* __restrict__ oracle,
             const float* __restrict__ w0, const float* __restrict__ b0,
             const float* __restrict__ hw, const float* __restrict__ hb,
             const float* __restrict__ ow, const float* __restrict__ ob,
             float* __restrict__ out) {
    extern __shared__ float hbuf[];          // [INDIM][TILE]
    __shared__ int   s_off[3][TILE][4];      // float4-unit offsets
    __shared__ float s_w[3][TILE][4];

    int tid = threadIdx.x;
    int blk = blockIdx.x;
    int b = blk >> 8;                        // 256 tiles per batch
    int n0 = (blk & 255) * TILE;

    // ---- positional encoding + oracle ----
    if (tid < TILE) {
        int r = tid;
        int n = n0 + r;
        float c0 = coords[2 * n], c1 = coords[2 * n + 1];
        hbuf[0 * TILE + r] = c0;
        hbuf[1 * TILE + r] = c1;
        float pf = 3.14159265358979323846f;
#pragma unroll
        for (int f = 0; f < 10; f++) {
            float s0, q0, s1, q1;
            sincosf(c0 * pf, &s0, &q0);
            sincosf(c1 * pf, &s1, &q1);
            hbuf[(2 + 4 * f + 0) * TILE + r] = s0;
            hbuf[(2 + 4 * f + 1) * TILE + r] = s1;
            hbuf[(2 + 4 * f + 2) * TILE + r] = q0;
            hbuf[(2 + 4 * f + 3) * TILE + r] = q1;
            pf *= 2.0f;
        }
#pragma unroll
        for (int j = 0; j < 3; j++)
            hbuf[(810 + j) * TILE + r] = oracle[((size_t)b * Nc + n) * 3 + j];
    }

    // ---- bilinear-sample metadata (3 levels x 32 samples) ----
    if (tid < 96) {
        int lvl = tid >> 5;
        int r = tid & 31;
        int n = n0 + r;
        int Hl = Hc >> lvl, Wl = Wc >> lvl;
        float c0 = coords[2 * n], c1 = coords[2 * n + 1];
        float y = (c0 + 1.0f) * 0.5f * (Hl - 1);
        float x = (c1 + 1.0f) * 0.5f * (Wl - 1);
        float y0f = fminf(fmaxf(floorf(y), 0.f), (float)(Hl - 1));
        float x0f = fminf(fmaxf(floorf(x), 0.f), (float)(Wl - 1));
        int y0 = (int)y0f, x0 = (int)x0f;
        int y1 = min(y0 + 1, Hl - 1), x1 = min(x0 + 1, Wl - 1);
        float wy = y - y0f, wx = x - x0f;
        int base = b * Hl * Wl;
        s_off[lvl][r][0] = (base + y0 * Wl + x0) * 64;
        s_off[lvl][r][1] = (base + y0 * Wl + x1) * 64;
        s_off[lvl][r][2] = (base + y1 * Wl + x0) * 64;
        s_off[lvl][r][3] = (base + y1 * Wl + x1) * 64;
        s_w[lvl][r][0] = (1.f - wy) * (1.f - wx);
        s_w[lvl][r][1] = (1.f - wy) * wx;
        s_w[lvl][r][2] = wy * (1.f - wx);
        s_w[lvl][r][3] = wy * wx;
    }
    __syncthreads();

    // ---- gather 3x256 feature channels ----
    {
        int r = tid & 31;
        int jl = tid >> 5;   // 0..7
        const float* srcs[3] = {grid, g_l1, g_l2};
#pragma unroll
        for (int lvl = 0; lvl < 3; lvl++) {
            const float4* src = (const float4*)srcs[lvl];
            int o0 = s_off[lvl][r][0], o1 = s_off[lvl][r][1];
            int o2 = s_off[lvl][r][2], o3 = s_off[lvl][r][3];
            float w0v = s_w[lvl][r][0], w1v = s_w[lvl][r][1];
            float w2v = s_w[lvl][r][2], w3v = s_w[lvl][r][3];
#pragma unroll
            for (int ch = 0; ch < 8; ch++) {
                int d4 = jl + 8 * ch;
                float4 a = __ldg(&src[o0 + d4]);
                float4 bb = __ldg(&src[o1 + d4]);
                float4 c = __ldg(&src[o2 + d4]);
                float4 d = __ldg(&src[o3 + d4]);
                int k = 42 + lvl * 256 + d4 * 4;
                hbuf[(k + 0) * TILE + r] = w0v * a.x + w1v * bb.x + w2v * c.x + w3v * d.x;
                hbuf[(k + 1) * TILE + r] = w0v * a.y + w1v * bb.y + w2v * c.y + w3v * d.y;
                hbuf[(k + 2) * TILE + r] = w0v * a.z + w1v * bb.z + w2v * c.z + w3v * d.z;
                hbuf[(k + 3) * TILE + r] = w0v * a.w + w1v * bb.w + w2v * c.w + w3v * d.w;
            }
        }
    }
    __syncthreads();

    float gamma = g_film[b * 512 + tid] + 1.0f;
    float beta  = g_film[b * 512 + 256 + tid];

    float acc[TILE];

    // ---- layer 0: 813 -> 256 ----
    gemm_cols(hbuf, w0 + tid, INDIM, acc);
    {
        float bias = b0[tid];
#pragma unroll
        for (int r = 0; r < TILE; r++)
            acc[r] = gelu_t((acc[r] + bias) * gamma + beta);
    }
    __syncthreads();
    {
        float4* row = (float4*)(hbuf + tid * TILE);
#pragma unroll
        for (int j = 0; j < 8; j++)
            row[j] = make_float4(acc[4 * j], acc[4 * j + 1], acc[4 * j + 2], acc[4 * j + 3]);
    }
    __syncthreads();

    // ---- hidden layers: 3 x (256 -> 256) ----
    for (int L = 0; L < 3; L++) {
        gemm_cols(hbuf, hw + L * MLPW * MLPW + tid, MLPW, acc);
        float bias = hb[L * MLPW + tid];
#pragma unroll
        for (int r = 0; r < TILE; r++)
            acc[r] = gelu_t((acc[r] + bias) * gamma + beta);
        __syncthreads();
        float4* row = (float4*)(hbuf + tid * TILE);
#pragma unroll
        for (int j = 0; j < 8; j++)
            row[j] = make_float4(acc[4 * j], acc[4 * j + 1], acc[4 * j + 2], acc[4 * j + 3]);
        __syncthreads();
    }

    // ---- output layer: 256 -> 3, tanh ----
    if (tid < 96) {
        int o = tid >> 5;    // 0..2
        int r = tid & 31;
        float a = ob[o];
        for (int k = 0; k < MLPW; k++)
            a = fmaf(hbuf[k * TILE + r], __ldg(ow + k * 3 + o), a);
        out[((size_t)b * Nc + n0 + r) * 3 + o] = tanhf(a);
    }
}

// ---------------- launch ----------------
extern "C" void kernel_launch(void* const* d_in, const int* in_sizes, int n_in,
                              void* d_out, int out_size) {
    const float* grid   = (const float*)d_in[0];
    const float* cv     = (const float*)d_in[1];
    const float* coords = (const float*)d_in[2];
    const float* oracle = (const float*)d_in[3];
    const float* w0     = (const float*)d_in[4];
    const float* b0     = (const float*)d_in[5];
    const float* hw     = (const float*)d_in[6];
    const float* hb     = (const float*)d_in[7];
    const float* cw     = (const float*)d_in[8];
    const float* cb     = (const float*)d_in[9];
    const float* ow     = (const float*)d_in[10];
    const float* ob     = (const float*)d_in[11];
    float* out = (float*)d_out;

    cudaFuncSetAttribute(fused_kernel, cudaFuncAttributeMaxDynamicSharedMemorySize, SMEM_BYTES);

    resize_w2_kernel<<<(Bc * Hc * 64 * 64 + 255) / 256, 256>>>(grid);
    resize_h2_kernel<<<(Bc * 64 * 64 * 64 + 255) / 256, 256>>>();
    resize_w4_kernel<<<(Bc * Hc * 32 * 64 + 255) / 256, 256>>>(grid);
    resize_h4_kernel<<<(Bc * 32 * 32 * 64 + 255) / 256, 256>>>();
    film_kernel<<<Bc, 512>>>(cv, cw, cb);
    fused_kernel<<<Bc * Nc / TILE, 256, SMEM_BYTES>>>(grid, coords, oracle,
                                                      w0, b0, hw, hb, ow, ob, out);
}

// round 2
// speedup vs baseline: 1.1991x; 1.1991x over previous
#include <cuda_runtime.h>
#include <math.h>
#include <stdint.h>

#define Bc    8
#define Hc    128
#define Wc    128
#define Dc    256
#define Nc    8192
#define MLPW  256
#define INDIM 813          // 2 + 40 + 768 + 3
#define TILE  32
#define SMEM_BYTES (INDIM * TILE * 4)

// ---------------- device scratch (static, allowed) ----------------
__device__ float g_t1[Bc * Hc * 64 * Dc];   // W-pass 128->64   (67 MB)
__device__ float g_l1[Bc * 64 * 64 * Dc];   // level1           (33 MB)
__device__ float g_t2[Bc * Hc * 32 * Dc];   // W-pass 128->32   (33 MB)
__device__ float g_l2[Bc * 32 * 32 * Dc];   // level2           (8 MB)
__device__ float g_film[Bc * 2 * MLPW];     // ctx @ ctx_w + ctx_b

// ---------------- f32x2 packed-FMA helpers ----------------
__device__ __forceinline__ uint64_t pack2(float x) {
    uint64_t r;
    asm("mov.b64 %0, {%1, %1};" : "=l"(r) : "f"(x));
    return r;
}
__device__ __forceinline__ void ffma2(uint64_t& d, uint64_t a, uint64_t b) {
    asm("fma.rn.f32x2 %0, %1, %2, %0;" : "+l"(d) : "l"(a), "l"(b));
}
__device__ __forceinline__ float2 unpack2(uint64_t v) {
    float2 r;
    asm("mov.b64 {%0, %1}, %2;" : "=f"(r.x), "=f"(r.y) : "l"(v));
    return r;
}

// ---------------- separable antialiased triangle resize ----------------
template <int INV, int HL, int WIN>
__device__ __forceinline__ void resize_w_body(const float* __restrict__ in,
                                              float* __restrict__ out) {
    const int WOUT = WIN / INV;
    const int NT = 2 * INV;
    int idx = blockIdx.x * blockDim.x + threadIdx.x;
    if (idx >= Bc * HL * WOUT * (Dc / 4)) return;
    int d4 = idx & 63;
    int t = idx >> 6;
    int xo = t % WOUT; t /= WOUT;
    int y = t % HL;
    int b = t / HL;

    float sf = (xo + 0.5f) * INV - 0.5f;
    int j0 = INV * xo - (INV / 2);
    float w[NT];
    float wsum = 0.f;
#pragma unroll
    for (int i = 0; i < NT; i++) {
        int j = j0 + i;
        float ww = 1.0f - fabsf((float)j - sf) * (1.0f / INV);
        ww = (j >= 0 && j < WIN) ? fmaxf(ww, 0.f) : 0.f;
        w[i] = ww;
        wsum += ww;
    }
    float inv = 1.0f / wsum;
    const float4* ip = (const float4*)in + ((size_t)(b * HL + y) * WIN) * 64 + d4;
    float4 acc = make_float4(0.f, 0.f, 0.f, 0.f);
#pragma unroll
    for (int i = 0; i < NT; i++) {
        if (w[i] > 0.f) {
            float4 v = __ldg(&ip[(j0 + i) * 64]);
            float ww = w[i] * inv;
            acc.x += ww * v.x; acc.y += ww * v.y;
            acc.z += ww * v.z; acc.w += ww * v.w;
        }
    }
    ((float4*)out)[((size_t)(b * HL + y) * WOUT + xo) * 64 + d4] = acc;
}

template <int INV, int HIN, int WL>
__device__ __forceinline__ void resize_h_body(const float* __restrict__ in,
                                              float* __restrict__ out) {
    const int HOUT = HIN / INV;
    const int NT = 2 * INV;
    int idx = blockIdx.x * blockDim.x + threadIdx.x;
    if (idx >= Bc * HOUT * WL * (Dc / 4)) return;
    int d4 = idx & 63;
    int t = idx >> 6;
    int x = t % WL; t /= WL;
    int yo = t % HOUT;
    int b = t / HOUT;

    float sf = (yo + 0.5f) * INV - 0.5f;
    int j0 = INV * yo - (INV / 2);
    float w[NT];
    float wsum = 0.f;
#pragma unroll
    for (int i = 0; i < NT; i++) {
        int j = j0 + i;
        float ww = 1.0f - fabsf((float)j - sf) * (1.0f / INV);
        ww = (j >= 0 && j < HIN) ? fmaxf(ww, 0.f) : 0.f;
        w[i] = ww;
        wsum += ww;
    }
    float inv = 1.0f / wsum;
    const float4* ip = (const float4*)in + ((size_t)b * HIN * WL + x) * 64 + d4;
    float4 acc = make_float4(0.f, 0.f, 0.f, 0.f);
#pragma unroll
    for (int i = 0; i < NT; i++) {
        if (w[i] > 0.f) {
            float4 v = __ldg(&ip[(size_t)(j0 + i) * WL * 64]);
            float ww = w[i] * inv;
            acc.x += ww * v.x; acc.y += ww * v.y;
            acc.z += ww * v.z; acc.w += ww * v.w;
        }
    }
    ((float4*)out)[((size_t)(b * HOUT + yo) * WL + x) * 64 + d4] = acc;
}

__global__ void resize_w2_kernel(const float* __restrict__ in) { resize_w_body<2, Hc, Wc>(in, g_t1); }
__global__ void resize_h2_kernel() { resize_h_body<2, Hc, 64>(g_t1, g_l1); }
__global__ void resize_w4_kernel(const float* __restrict__ in) { resize_w_body<4, Hc, Wc>(in, g_t2); }
__global__ void resize_h4_kernel() { resize_h_body<4, Hc, 32>(g_t2, g_l2); }

// ---------------- FiLM: ctx = context_vector @ ctx_w + ctx_b ----------------
__global__ void film_kernel(const float* __restrict__ cv,
                            const float* __restrict__ cw,
                            const float* __restrict__ cb) {
    int b = blockIdx.x;
    int j = threadIdx.x;             // 512 threads
    float acc = cb[j];
    for (int k = 0; k < Dc; k++)
        acc = fmaf(cv[b * Dc + k], cw[k * 512 + j], acc);
    g_film[b * 512 + j] = acc;
}

// ---------------- fused gather + MLP ----------------
__device__ __forceinline__ float gelu_t(float x) {
    float x3 = x * x * x;
    float t = tanhf(0.7978845608028654f * (x + 0.044715f * x3));
    return 0.5f * x * (1.0f + t);
}

// GEMM: thread owns columns (c0, c0+1) and samples [s0, s0+16).
// Per k: 1 LDG.64 (2 weights), 4 LDS.128 (16 samples as 8 u64), 16 FFMA2.
__device__ __forceinline__ void gemm2(const float* __restrict__ hbuf,
                                      const float* __restrict__ w,
                                      int K, int c0, int s0,
                                      uint64_t acc[2][8]) {
#pragma unroll
    for (int c = 0; c < 2; c++)
#pragma unroll
        for (int j = 0; j < 8; j++) acc[c][j] = 0ull;
    const float* hb = hbuf + s0;
#pragma unroll 4
    for (int k = 0; k < K; k++) {
        float2 wv = *(const float2*)(w + (size_t)k * MLPW + c0);
        uint64_t w0p = pack2(wv.x);
        uint64_t w1p = pack2(wv.y);
        const ulonglong2* hr = (const ulonglong2*)(hb + k * TILE);
#pragma unroll
        for (int j = 0; j < 4; j++) {
            ulonglong2 hv = hr[j];
            ffma2(acc[0][2 * j + 0], w0p, hv.x);
            ffma2(acc[0][2 * j + 1], w0p, hv.y);
            ffma2(acc[1][2 * j + 0], w1p, hv.x);
            ffma2(acc[1][2 * j + 1], w1p, hv.y);
        }
    }
}

// gelu((acc + bias) * gamma + beta) then store back to hbuf[col][sample].
__device__ __forceinline__ void act_store(uint64_t acc[2][8],
                                          float bias0, float bias1,
                                          float2 gm, float2 bt,
                                          float* hbuf, int c0, int s0) {
    float v[2][16];
#pragma unroll
    for (int c = 0; c < 2; c++) {
        float bias = c ? bias1 : bias0;
        float g = c ? gm.y : gm.x;
        float be = c ? bt.y : bt.x;
#pragma unroll
        for (int j = 0; j < 8; j++) {
            float2 p = unpack2(acc[c][j]);
            v[c][2 * j + 0] = gelu_t((p.x + bias) * g + be);
            v[c][2 * j + 1] = gelu_t((p.y + bias) * g + be);
        }
    }
    __syncthreads();
#pragma unroll
    for (int c = 0; c < 2; c++) {
        float4* dst = (float4*)(hbuf + (c0 + c) * TILE + s0);
#pragma unroll
        for (int j = 0; j < 4; j++)
            dst[j] = make_float4(v[c][4 * j + 0], v[c][4 * j + 1],
                                 v[c][4 * j + 2], v[c][4 * j + 3]);
    }
    __syncthreads();
}

__global__ void __launch_bounds__(256)
fused_kernel(const float* __restrict__ grid,
             const float* __restrict__ coords,
             const float* __restrict__ oracle,
             const float* __restrict__ w0, const float* __restrict__ b0,
             const float* __restrict__ hw, const float* __restrict__ hb,
             const float* __restrict__ ow, const float* __restrict__ ob,
             float* __restrict__ out) {
    extern __shared__ float hbuf[];          // [INDIM][TILE]
    __shared__ int   s_off[3][TILE][4];      // float4-unit offsets
    __shared__ float s_w[3][TILE][4];

    int tid = threadIdx.x;
    int blk = blockIdx.x;
    int b = blk >> 8;                        // 256 tiles per batch
    int n0 = (blk & 255) * TILE;

    // ---- positional encoding + oracle ----
    if (tid < TILE) {
        int r = tid;
        int n = n0 + r;
        float c0 = coords[2 * n], c1 = coords[2 * n + 1];
        hbuf[0 * TILE + r] = c0;
        hbuf[1 * TILE + r] = c1;
        float pf = 3.14159265358979323846f;
#pragma unroll
        for (int f = 0; f < 10; f++) {
            float s0, q0, s1, q1;
            sincosf(c0 * pf, &s0, &q0);
            sincosf(c1 * pf, &s1, &q1);
            hbuf[(2 + 4 * f + 0) * TILE + r] = s0;
            hbuf[(2 + 4 * f + 1) * TILE + r] = s1;
            hbuf[(2 + 4 * f + 2) * TILE + r] = q0;
            hbuf[(2 + 4 * f + 3) * TILE + r] = q1;
            pf *= 2.0f;
        }
#pragma unroll
        for (int j = 0; j < 3; j++)
            hbuf[(810 + j) * TILE + r] = oracle[((size_t)b * Nc + n) * 3 + j];
    }

    // ---- bilinear-sample metadata (3 levels x 32 samples) ----
    if (tid < 96) {
        int lvl = tid >> 5;
        int r = tid & 31;
        int n = n0 + r;
        int Hl = Hc >> lvl, Wl = Wc >> lvl;
        float c0 = coords[2 * n], c1 = coords[2 * n + 1];
        float y = (c0 + 1.0f) * 0.5f * (Hl - 1);
        float x = (c1 + 1.0f) * 0.5f * (Wl - 1);
        float y0f = fminf(fmaxf(floorf(y), 0.f), (float)(Hl - 1));
        float x0f = fminf(fmaxf(floorf(x), 0.f), (float)(Wl - 1));
        int y0 = (int)y0f, x0 = (int)x0f;
        int y1 = min(y0 + 1, Hl - 1), x1 = min(x0 + 1, Wl - 1);
        float wy = y - y0f, wx = x - x0f;
        int base = b * Hl * Wl;
        s_off[lvl][r][0] = (base + y0 * Wl + x0) * 64;
        s_off[lvl][r][1] = (base + y0 * Wl + x1) * 64;
        s_off[lvl][r][2] = (base + y1 * Wl + x0) * 64;
        s_off[lvl][r][3] = (base + y1 * Wl + x1) * 64;
        s_w[lvl][r][0] = (1.f - wy) * (1.f - wx);
        s_w[lvl][r][1] = (1.f - wy) * wx;
        s_w[lvl][r][2] = wy * (1.f - wx);
        s_w[lvl][r][3] = wy * wx;
    }
    __syncthreads();

    // ---- gather 3x256 feature channels ----
    {
        int r = tid & 31;
        int jl = tid >> 5;   // 0..7
        const float* srcs[3] = {grid, g_l1, g_l2};
#pragma unroll
        for (int lvl = 0; lvl < 3; lvl++) {
            const float4* src = (const float4*)srcs[lvl];
            int o0 = s_off[lvl][r][0], o1 = s_off[lvl][r][1];
            int o2 = s_off[lvl][r][2], o3 = s_off[lvl][r][3];
            float w0v = s_w[lvl][r][0], w1v = s_w[lvl][r][1];
            float w2v = s_w[lvl][r][2], w3v = s_w[lvl][r][3];
#pragma unroll
            for (int ch = 0; ch < 8; ch++) {
                int d4 = jl + 8 * ch;
                float4 a = __ldg(&src[o0 + d4]);
                float4 bb = __ldg(&src[o1 + d4]);
                float4 c = __ldg(&src[o2 + d4]);
                float4 d = __ldg(&src[o3 + d4]);
                int k = 42 + lvl * 256 + d4 * 4;
                hbuf[(k + 0) * TILE + r] = w0v * a.x + w1v * bb.x + w2v * c.x + w3v * d.x;
                hbuf[(k + 1) * TILE + r] = w0v * a.y + w1v * bb.y + w2v * c.y + w3v * d.y;
                hbuf[(k + 2) * TILE + r] = w0v * a.z + w1v * bb.z + w2v * c.z + w3v * d.z;
                hbuf[(k + 3) * TILE + r] = w0v * a.w + w1v * bb.w + w2v * c.w + w3v * d.w;
            }
        }
    }
    __syncthreads();

    int c0 = (tid & 127) * 2;     // column pair
    int s0 = (tid >> 7) * 16;     // sample half

    float2 gm = make_float2(g_film[b * 512 + c0] + 1.0f,
                            g_film[b * 512 + c0 + 1] + 1.0f);
    float2 bt = make_float2(g_film[b * 512 + 256 + c0],
                            g_film[b * 512 + 256 + c0 + 1]);

    uint64_t acc[2][8];

    // ---- layer 0: 813 -> 256 ----
    gemm2(hbuf, w0, INDIM, c0, s0, acc);
    act_store(acc, b0[c0], b0[c0 + 1], gm, bt, hbuf, c0, s0);

    // ---- hidden layers: 3 x (256 -> 256) ----
#pragma unroll
    for (int L = 0; L < 3; L++) {
        gemm2(hbuf, hw + (size_t)L * MLPW * MLPW, MLPW, c0, s0, acc);
        act_store(acc, hb[L * MLPW + c0], hb[L * MLPW + c0 + 1], gm, bt,
                  hbuf, c0, s0);
    }

    // ---- output layer: 256 -> 3, tanh ----
    if (tid < 96) {
        int o = tid >> 5;    // 0..2
        int r = tid & 31;
        float a = ob[o];
        for (int k = 0; k < MLPW; k++)
            a = fmaf(hbuf[k * TILE + r], __ldg(ow + k * 3 + o), a);
        out[((size_t)b * Nc + n0 + r) * 3 + o] = tanhf(a);
    }
}

// ---------------- launch ----------------
extern "C" void kernel_launch(void* const* d_in, const int* in_sizes, int n_in,
                              void* d_out, int out_size) {
    const float* grid   = (const float*)d_in[0];
    const float* cv     = (const float*)d_in[1];
    const float* coords = (const float*)d_in[2];
    const float* oracle = (const float*)d_in[3];
    const float* w0     = (const float*)d_in[4];
    const float* b0     = (const float*)d_in[5];
    const float* hw     = (const float*)d_in[6];
    const float* hb     = (const float*)d_in[7];
    const float* cw     = (const float*)d_in[8];
    const float* cb     = (const float*)d_in[9];
    const float* ow     = (const float*)d_in[10];
    const float* ob     = (const float*)d_in[11];
    float* out = (float*)d_out;

    cudaFuncSetAttribute(fused_kernel, cudaFuncAttributeMaxDynamicSharedMemorySize, SMEM_BYTES);

    resize_w2_kernel<<<(Bc * Hc * 64 * 64 + 255) / 256, 256>>>(grid);
    resize_h2_kernel<<<(Bc * 64 * 64 * 64 + 255) / 256, 256>>>();
    resize_w4_kernel<<<(Bc * Hc * 32 * 64 + 255) / 256, 256>>>(grid);
    resize_h4_kernel<<<(Bc * 32 * 32 * 64 + 255) / 256, 256>>>();
    film_kernel<<<Bc, 512>>>(cv, cw, cb);
    fused_kernel<<<Bc * Nc / TILE, 256, SMEM_BYTES>>>(grid, coords, oracle,
                                                      w0, b0, hw, hb, ow, ob, out);
}